// round 6
// baseline (speedup 1.0000x reference)
#include <cuda_runtime.h>
#include <math.h>

#define KS   9        // k-splits
#define DC   128      // d-chunk staged per iteration
#define STR  132      // smem row stride (floats), pad 4 -> conflict-free
#define NQ   200
#define NGT  32
#define DTOT 65536
#define CHTOT (DTOT/DC)   // 512 chunks total along d

// ---- scratch (static __device__, per allocation rules) ----
__device__ float g_part[KS * 4 * NQ * NGT];   // per-ksplit partial inter
__device__ float g_psum[KS * 4 * NQ];         // per-ksplit partial sigmoid row sums
__device__ float g_gtsum[4 * NGT];

__device__ __forceinline__ float sigf(float x) {
    return __fdividef(1.0f, 1.0f + __expf(-x));
}
__device__ __forceinline__ void ffma2(unsigned long long& d,
                                      unsigned long long a,
                                      unsigned long long b) {
    asm("fma.rn.f32x2 %0, %1, %2, %0;" : "+l"(d) : "l"(a), "l"(b));
}

extern __shared__ float sm[];

// ---------------------------------------------------------------------------
// Kernel A: sigmoid + K-split GEMM.  grid(KS, 4 qtiles, 4 batches), 256 thr.
// Block tile: 64 q x 32 n over its 1/KS share of d.
// ---------------------------------------------------------------------------
__global__ void __launch_bounds__(256, 1)
kA(const float* __restrict__ pm, const float* __restrict__ gt) {
    const int ks = blockIdx.x, qt = blockIdx.y, b = blockIdx.z;
    const int q0 = qt * 64;
    const int tid = threadIdx.x;

    float* pmS = sm;                    // [64][STR]
    float* gtS = sm + 64 * STR;         // [32][STR]
    float* psW = gtS + NGT * STR;       // [64] per-q sigmoid sums

    for (int i = tid; i < 64; i += 256) psW[i] = 0.f;
    __syncthreads();

    const int lane = tid & 31;
    const int wz   = tid >> 5;      // warp = d-slice 0..7
    const int qtr  = lane & 7;      // q-thread 0..7
    const int ntr  = lane >> 3;     // n-thread 0..3

    unsigned long long acc[8][8];
    #pragma unroll
    for (int i = 0; i < 8; i++)
        #pragma unroll
        for (int j = 0; j < 8; j++) acc[i][j] = 0ull;

    const int c0 = (ks * CHTOT) / KS;
    const int c1 = ((ks + 1) * CHTOT) / KS;

    for (int c = c0; c < c1; c++) {
        const int kb = c * DC;

        // ---- stage pm [64][DC] with sigmoid; accumulate row sums ----
        #pragma unroll
        for (int it = 0; it < 8; it++) {
            int f = tid + it * 256;
            int q = f >> 5;          // == wz + 8*it (warp-uniform)
            int col = f & 31;
            float4 v = make_float4(0.f, 0.f, 0.f, 0.f);
            float ls = 0.f;
            if (q0 + q < NQ) {
                float4 r = *reinterpret_cast<const float4*>(
                    pm + (size_t)(b * NQ + q0 + q) * DTOT + kb + col * 4);
                v.x = sigf(r.x); v.y = sigf(r.y); v.z = sigf(r.z); v.w = sigf(r.w);
                ls = (v.x + v.y) + (v.z + v.w);
            }
            *reinterpret_cast<float4*>(&pmS[q * STR + col * 4]) = v;
            #pragma unroll
            for (int off = 16; off; off >>= 1)
                ls += __shfl_down_sync(0xffffffffu, ls, off);
            if (lane == 0) psW[q] += ls;   // unique (wz,it) -> unique q: no race
        }

        // ---- stage gt [32][DC] ----
        #pragma unroll
        for (int it = 0; it < 4; it++) {
            int f = tid + it * 256;
            int n = f >> 5, col = f & 31;
            *reinterpret_cast<float4*>(&gtS[n * STR + col * 4]) =
                *reinterpret_cast<const float4*>(
                    gt + (size_t)(b * NGT + n) * DTOT + kb + col * 4);
        }
        __syncthreads();

        // ---- compute: warp wz covers d in [wz*16, wz*16+16) ----
        const int db = wz * 16;
        #pragma unroll
        for (int s = 0; s < 4; s++) {
            const int d = db + s * 4;
            ulonglong2 g2[8];
            #pragma unroll
            for (int j = 0; j < 8; j++)
                g2[j] = *reinterpret_cast<const ulonglong2*>(
                    &gtS[(ntr + 4 * j) * STR + d]);
            #pragma unroll
            for (int i = 0; i < 8; i++) {
                ulonglong2 p2 = *reinterpret_cast<const ulonglong2*>(
                    &pmS[(qtr + 8 * i) * STR + d]);
                #pragma unroll
                for (int j = 0; j < 8; j++) {
                    ffma2(acc[i][j], p2.x, g2[j].x);
                    ffma2(acc[i][j], p2.y, g2[j].y);
                }
            }
        }
        __syncthreads();
    }

    // ---- deterministic cross-warp reduction via smem (reuse sm[0..8191]) ----
    float* red = sm;   // [4][2048]; psW lives at 12672+ so it's untouched
    if (wz < 4) {
        #pragma unroll
        for (int i = 0; i < 8; i++)
            #pragma unroll
            for (int j = 0; j < 8; j++) {
                float2 f2 = *reinterpret_cast<float2*>(&acc[i][j]);
                red[wz * 2048 + (qtr + 8 * i) * 32 + (ntr + 4 * j)] = f2.x + f2.y;
            }
    }
    __syncthreads();
    if (wz >= 4) {
        #pragma unroll
        for (int i = 0; i < 8; i++)
            #pragma unroll
            for (int j = 0; j < 8; j++) {
                float2 f2 = *reinterpret_cast<float2*>(&acc[i][j]);
                red[(wz - 4) * 2048 + (qtr + 8 * i) * 32 + (ntr + 4 * j)] += f2.x + f2.y;
            }
    }
    __syncthreads();

    for (int o = tid; o < 2048; o += 256) {
        float s = red[o] + red[2048 + o] + red[4096 + o] + red[6144 + o];
        int q = o >> 5;
        if (q0 + q < NQ)
            g_part[((size_t)(ks * 4 + b) * NQ + q0 + q) * 32 + (o & 31)] = s;
    }
    if (tid < 64 && q0 + tid < NQ)
        g_psum[(ks * 4 + b) * NQ + q0 + tid] = psW[tid];
}

// ---------------------------------------------------------------------------
// Kernel GT: per-(b,n) gt row sums. grid(128), 256 threads.
// ---------------------------------------------------------------------------
__global__ void __launch_bounds__(256)
kG(const float* __restrict__ gt) {
    const float4* p = reinterpret_cast<const float4*>(gt + (size_t)blockIdx.x * DTOT);
    float s = 0.f;
    for (int i = threadIdx.x; i < DTOT / 4; i += 256) {
        float4 v = p[i];
        s += (v.x + v.y) + (v.z + v.w);
    }
    __shared__ float r[256];
    r[threadIdx.x] = s;
    __syncthreads();
    for (int o = 128; o; o >>= 1) {
        if (threadIdx.x < o) r[threadIdx.x] += r[threadIdx.x + o];
        __syncthreads();
    }
    if (threadIdx.x == 0) g_gtsum[blockIdx.x] = r[0];
}

// ---------------------------------------------------------------------------
// Kernel C: combine + per-column top-4 + greedy dedup + output. grid(4).
// OUTPUT IS float32 (harness __output__ dtype): src||tgt||valid as floats.
// ---------------------------------------------------------------------------
__global__ void __launch_bounds__(256)
kC(const float* __restrict__ logits, float* __restrict__ out) {
    const int b = blockIdx.x, tid = threadIdx.x;
    __shared__ float comb[NQ * NGT];
    __shared__ float psS[NQ], clsS[NQ], gsS[NGT];
    __shared__ int top4[NGT * 4];
    __shared__ unsigned char assigned[NQ];

    if (tid < NQ) {
        float s = 0.f;
        #pragma unroll
        for (int z = 0; z < KS; z++) s += g_psum[(z * 4 + b) * NQ + tid];
        psS[tid] = s;
        float l0 = logits[(b * NQ + tid) * 2 + 0];
        float l1 = logits[(b * NQ + tid) * 2 + 1];
        clsS[tid] = 1.0f / (1.0f + expf(l0 - l1));   // softmax(...)[1]
    }
    if (tid < NGT) gsS[tid] = g_gtsum[b * NGT + tid];
    __syncthreads();

    for (int o = tid; o < NQ * NGT; o += 256) {
        float inter = 0.f;
        #pragma unroll
        for (int z = 0; z < KS; z++)
            inter += g_part[(size_t)(z * 4 + b) * NQ * 32 + o];
        comb[o] = inter / (psS[o >> 5] + gsS[o & 31] - inter + 1e-6f) * clsS[o >> 5];
    }
    __syncthreads();

    // per-column top-4 (warp w handles columns 4w..4w+3); tie -> lower q
    const int w = tid >> 5, lane = tid & 31;
    for (int n = w * 4; n < w * 4 + 4; n++) {
        float v[7];
        #pragma unroll
        for (int t = 0; t < 7; t++) {
            int q = lane + 32 * t;
            v[t] = (q < NQ) ? comb[q * 32 + n] : -1e30f;
        }
        unsigned selmask = 0;
        for (int kk = 0; kk < 4; kk++) {
            float bv = -1e30f; int bq = 1 << 20;
            #pragma unroll
            for (int t = 0; t < 7; t++) {
                int q = lane + 32 * t;
                if (!((selmask >> t) & 1) && q < NQ) {
                    if (v[t] > bv || (v[t] == bv && q < bq)) { bv = v[t]; bq = q; }
                }
            }
            for (int off = 16; off; off >>= 1) {
                float ov = __shfl_xor_sync(0xffffffffu, bv, off);
                int   oq = __shfl_xor_sync(0xffffffffu, bq, off);
                if (ov > bv || (ov == bv && oq < bq)) { bv = ov; bq = oq; }
            }
            if (lane == 0) top4[n * 4 + kk] = bq;
            if ((bq & 31) == lane) selmask |= 1u << (bq >> 5);
        }
    }
    __syncthreads();

    // greedy dedup across GT columns (serial, matches reference scan order)
    if (tid == 0) {
        for (int q = 0; q < NQ; q++) assigned[q] = 0;
        for (int n = 0; n < NGT; n++)
            for (int kk = 0; kk < 4; kk++) {
                int idx = top4[n * 4 + kk];
                int sel = assigned[idx] ? -1 : idx;
                assigned[idx] = 1;
                int o = (b * NGT + n) * 4 + kk;
                out[o]        = (float)sel;                    // src_idx
                out[512 + o]  = (sel >= 0) ? (float)n : -1.0f; // tgt_idx
                out[1024 + o] = (sel >= 0) ? 1.0f : 0.0f;      // valid
            }
    }
}

extern "C" void kernel_launch(void* const* d_in, const int* in_sizes, int n_in,
                              void* d_out, int out_size) {
    const float* pm = (const float*)d_in[0];   // [4,200,256,256]
    const float* lg = (const float*)d_in[1];   // [4,200,2]
    const float* gt = (const float*)d_in[2];   // [4,32,256,256]
    float* out = (float*)d_out;

    const int smemA = (64 * STR + NGT * STR + 64) * sizeof(float);  // 50944 B
    cudaFuncSetAttribute(kA, cudaFuncAttributeMaxDynamicSharedMemorySize, smemA);

    kA<<<dim3(KS, 4, 4), 256, smemA>>>(pm, gt);
    kG<<<128, 256>>>(gt);
    kC<<<4, 256>>>(lg, out);
}

// round 7
// speedup vs baseline: 1.6697x; 1.6697x over previous
#include <cuda_runtime.h>
#include <math.h>

#define KS   9        // k-splits
#define DC   128      // d-chunk staged per iteration
#define STR  132      // smem row stride (floats), pad 4 -> conflict-free
#define NQ   200
#define NGT  32
#define DTOT 65536
#define CHTOT (DTOT/DC)   // 512 chunks along d

// ---- scratch (static __device__, per allocation rules) ----
__device__ float g_part[KS * 4 * NQ * NGT];   // per-ksplit partial inter
__device__ float g_psum[KS * 4 * NQ];         // per-ksplit partial sigmoid row sums
__device__ float g_gtsum[4 * NGT];

__device__ __forceinline__ float sigf(float x) {
    return __fdividef(1.0f, 1.0f + __expf(-x));
}
__device__ __forceinline__ void ffma2(unsigned long long& d,
                                      unsigned long long a,
                                      unsigned long long b) {
    asm("fma.rn.f32x2 %0, %1, %2, %0;" : "+l"(d) : "l"(a), "l"(b));
}

extern __shared__ float sm[];

// ---------------------------------------------------------------------------
// Kernel A: sigmoid + K-split GEMM.  grid(KS, 4 qtiles, 4 batches), 256 thr.
// Block tile: 64 q x 32 n over its 1/KS share of d. Warp wz owns d-slice
// [wz*16, wz*16+16) of each 128-d chunk; per-thread 8q x 8n f32x2 accums.
// ---------------------------------------------------------------------------
__global__ void __launch_bounds__(256, 1)
kA(const float* __restrict__ pm, const float* __restrict__ gt) {
    const int ks = blockIdx.x, qt = blockIdx.y, b = blockIdx.z;
    const int q0 = qt * 64;
    const int tid = threadIdx.x;

    float* pmS = sm;                 // [64][STR]
    float* gtS = sm + 64 * STR;      // [32][STR]

    const int lane = tid & 31;
    const int wz   = tid >> 5;       // warp = d-slice 0..7
    const int qtr  = lane & 7;       // q-thread 0..7
    const int ntr  = lane >> 3;      // n-thread 0..3

    unsigned long long acc[8][8];
    #pragma unroll
    for (int i = 0; i < 8; i++)
        #pragma unroll
        for (int j = 0; j < 8; j++) acc[i][j] = 0ull;

    float rowsum[8];
    #pragma unroll
    for (int i = 0; i < 8; i++) rowsum[i] = 0.f;

    // staging coords: pm row q = wz + 8*it (it 0..7), gt row n = wz + 8*it (it 0..3),
    // columns = lane*4 .. lane*4+3 (float4)
    unsigned vm = 0;
    #pragma unroll
    for (int it = 0; it < 8; it++)
        if (q0 + wz + 8 * it < NQ) vm |= 1u << it;

    const size_t pmRow = (size_t)(b * NQ + q0 + wz) * DTOT + (size_t)lane * 4;
    const size_t gtRow = (size_t)(b * NGT + wz) * DTOT + (size_t)lane * 4;

    const int c0 = (ks * CHTOT) / KS;
    const int c1 = ((ks + 1) * CHTOT) / KS;

    for (int c = c0; c < c1; c++) {
        const int kb = c * DC;

        // ---- issue all global loads first (MLP = 12) ----
        float4 rg[4];
        #pragma unroll
        for (int it = 0; it < 4; it++)
            rg[it] = *reinterpret_cast<const float4*>(
                gt + gtRow + (size_t)it * 8 * DTOT + kb);
        float4 rp[8];
        #pragma unroll
        for (int it = 0; it < 8; it++)
            if ((vm >> it) & 1)
                rp[it] = *reinterpret_cast<const float4*>(
                    pm + pmRow + (size_t)it * 8 * DTOT + kb);

        // ---- sigmoid + store pm; accumulate per-row sums in registers ----
        #pragma unroll
        for (int it = 0; it < 8; it++) {
            float4 v;
            if ((vm >> it) & 1) {
                v.x = sigf(rp[it].x); v.y = sigf(rp[it].y);
                v.z = sigf(rp[it].z); v.w = sigf(rp[it].w);
                rowsum[it] += (v.x + v.y) + (v.z + v.w);
            } else {
                v = make_float4(0.f, 0.f, 0.f, 0.f);
            }
            *reinterpret_cast<float4*>(&pmS[(wz + 8 * it) * STR + lane * 4]) = v;
        }
        #pragma unroll
        for (int it = 0; it < 4; it++)
            *reinterpret_cast<float4*>(&gtS[(wz + 8 * it) * STR + lane * 4]) = rg[it];
        __syncthreads();

        // ---- compute: warp wz covers d in [wz*16, wz*16+16) ----
        const int db = wz * 16;
        #pragma unroll
        for (int s = 0; s < 4; s++) {
            const int d = db + s * 4;
            ulonglong2 g2[8];
            #pragma unroll
            for (int j = 0; j < 8; j++)
                g2[j] = *reinterpret_cast<const ulonglong2*>(
                    &gtS[(ntr + 4 * j) * STR + d]);
            #pragma unroll
            for (int i = 0; i < 8; i++) {
                ulonglong2 p2 = *reinterpret_cast<const ulonglong2*>(
                    &pmS[(qtr + 8 * i) * STR + d]);
                #pragma unroll
                for (int j = 0; j < 8; j++) {
                    ffma2(acc[i][j], p2.x, g2[j].x);
                    ffma2(acc[i][j], p2.y, g2[j].y);
                }
            }
        }
        __syncthreads();
    }

    // ---- deterministic cross-warp reduction via smem (reuse sm[0..8191]) ----
    float* red = sm;   // [4][2048] floats, fits inside pmS region
    if (wz < 4) {
        #pragma unroll
        for (int i = 0; i < 8; i++)
            #pragma unroll
            for (int j = 0; j < 8; j++) {
                float2 f2 = *reinterpret_cast<float2*>(&acc[i][j]);
                red[wz * 2048 + (qtr + 8 * i) * 32 + (ntr + 4 * j)] = f2.x + f2.y;
            }
    }
    __syncthreads();
    if (wz >= 4) {
        #pragma unroll
        for (int i = 0; i < 8; i++)
            #pragma unroll
            for (int j = 0; j < 8; j++) {
                float2 f2 = *reinterpret_cast<float2*>(&acc[i][j]);
                red[(wz - 4) * 2048 + (qtr + 8 * i) * 32 + (ntr + 4 * j)] += f2.x + f2.y;
            }
    }
    __syncthreads();

    for (int o = tid; o < 2048; o += 256) {
        float s = red[o] + red[2048 + o] + red[4096 + o] + red[6144 + o];
        int q = o >> 5;
        if (q0 + q < NQ)
            g_part[((size_t)(ks * 4 + b) * NQ + q0 + q) * 32 + (o & 31)] = s;
    }

    // ---- per-q sigmoid sums: warp-reduce register partials (q warp-uniform) ----
    #pragma unroll
    for (int it = 0; it < 8; it++) {
        float s = rowsum[it];
        #pragma unroll
        for (int off = 16; off; off >>= 1)
            s += __shfl_down_sync(0xffffffffu, s, off);
        if (lane == 0 && ((vm >> it) & 1))
            g_psum[(ks * 4 + b) * NQ + q0 + wz + 8 * it] = s;
    }
}

// ---------------------------------------------------------------------------
// Kernel GT: per-(b,n) gt row sums. grid(128), 256 threads.
// ---------------------------------------------------------------------------
__global__ void __launch_bounds__(256)
kG(const float* __restrict__ gt) {
    const float4* p = reinterpret_cast<const float4*>(gt + (size_t)blockIdx.x * DTOT);
    float s = 0.f;
    for (int i = threadIdx.x; i < DTOT / 4; i += 256) {
        float4 v = p[i];
        s += (v.x + v.y) + (v.z + v.w);
    }
    __shared__ float r[256];
    r[threadIdx.x] = s;
    __syncthreads();
    for (int o = 128; o; o >>= 1) {
        if (threadIdx.x < o) r[threadIdx.x] += r[threadIdx.x + o];
        __syncthreads();
    }
    if (threadIdx.x == 0) g_gtsum[blockIdx.x] = r[0];
}

// ---------------------------------------------------------------------------
// Kernel C: combine + per-column top-4 + greedy dedup + output. grid(4).
// OUTPUT is float32: src||tgt||valid as floats (512 each).
// ---------------------------------------------------------------------------
__global__ void __launch_bounds__(256)
kC(const float* __restrict__ logits, float* __restrict__ out) {
    const int b = blockIdx.x, tid = threadIdx.x;
    __shared__ float comb[NQ * NGT];
    __shared__ float psS[NQ], clsS[NQ], gsS[NGT];
    __shared__ int top4[NGT * 4];
    __shared__ unsigned char assigned[NQ];

    if (tid < NQ) {
        float s = 0.f;
        #pragma unroll
        for (int z = 0; z < KS; z++) s += g_psum[(z * 4 + b) * NQ + tid];
        psS[tid] = s;
        float l0 = logits[(b * NQ + tid) * 2 + 0];
        float l1 = logits[(b * NQ + tid) * 2 + 1];
        clsS[tid] = 1.0f / (1.0f + expf(l0 - l1));   // softmax(...)[1]
    }
    if (tid < NGT) gsS[tid] = g_gtsum[b * NGT + tid];
    __syncthreads();

    for (int o = tid; o < NQ * NGT; o += 256) {
        float inter = 0.f;
        #pragma unroll
        for (int z = 0; z < KS; z++)
            inter += g_part[(size_t)(z * 4 + b) * NQ * 32 + o];
        comb[o] = inter / (psS[o >> 5] + gsS[o & 31] - inter + 1e-6f) * clsS[o >> 5];
    }
    __syncthreads();

    // per-column top-4 (warp w handles columns 4w..4w+3); tie -> lower q
    const int w = tid >> 5, lane = tid & 31;
    for (int n = w * 4; n < w * 4 + 4; n++) {
        float v[7];
        #pragma unroll
        for (int t = 0; t < 7; t++) {
            int q = lane + 32 * t;
            v[t] = (q < NQ) ? comb[q * 32 + n] : -1e30f;
        }
        unsigned selmask = 0;
        for (int kk = 0; kk < 4; kk++) {
            float bv = -1e30f; int bq = 1 << 20;
            #pragma unroll
            for (int t = 0; t < 7; t++) {
                int q = lane + 32 * t;
                if (!((selmask >> t) & 1) && q < NQ) {
                    if (v[t] > bv || (v[t] == bv && q < bq)) { bv = v[t]; bq = q; }
                }
            }
            for (int off = 16; off; off >>= 1) {
                float ov = __shfl_xor_sync(0xffffffffu, bv, off);
                int   oq = __shfl_xor_sync(0xffffffffu, bq, off);
                if (ov > bv || (ov == bv && oq < bq)) { bv = ov; bq = oq; }
            }
            if (lane == 0) top4[n * 4 + kk] = bq;
            if ((bq & 31) == lane) selmask |= 1u << (bq >> 5);
        }
    }
    __syncthreads();

    // greedy dedup across GT columns (serial, matches reference scan order)
    if (tid == 0) {
        for (int q = 0; q < NQ; q++) assigned[q] = 0;
        for (int n = 0; n < NGT; n++)
            for (int kk = 0; kk < 4; kk++) {
                int idx = top4[n * 4 + kk];
                int sel = assigned[idx] ? -1 : idx;
                assigned[idx] = 1;
                int o = (b * NGT + n) * 4 + kk;
                out[o]        = (float)sel;                    // src_idx
                out[512 + o]  = (sel >= 0) ? (float)n : -1.0f; // tgt_idx
                out[1024 + o] = (sel >= 0) ? 1.0f : 0.0f;      // valid
            }
    }
}

extern "C" void kernel_launch(void* const* d_in, const int* in_sizes, int n_in,
                              void* d_out, int out_size) {
    const float* pm = (const float*)d_in[0];   // [4,200,256,256]
    const float* lg = (const float*)d_in[1];   // [4,200,2]
    const float* gt = (const float*)d_in[2];   // [4,32,256,256]
    float* out = (float*)d_out;

    const int smemA = (96 * STR) * sizeof(float);  // 50688 B
    cudaFuncSetAttribute(kA, cudaFuncAttributeMaxDynamicSharedMemorySize, smemA);

    kA<<<dim3(KS, 4, 4), 256, smemA>>>(pm, gt);
    kG<<<128, 256>>>(gt);
    kC<<<4, 256>>>(lg, out);
}